// round 1
// baseline (speedup 1.0000x reference)
#include <cuda_runtime.h>
#include <cstdint>

// ---------------------------------------------------------------------------
// CNF_59133109731627 : continuous normalizing flow step
//   Hypernet:  p1 = tanh(t*W1 + b1)            (512)
//              p2 = tanh(p1 @ W2 + b2)          (512)
//              p3 = p2 @ W3 + b3                (12352)
//   Params:    W = p3[0:4096]       as (64,64)
//              U = p3[4096:8192]*sigmoid(p3[8192:12288])  (64,64)
//              B = p3[12288:12352]  (64)
//              wu[w] = sum_d W[w,d]*U[w,d]
//   Main:      h[b,w]  = tanh(sum_d z[b,d]W[w,d] + B[w])
//              dz[b,d] = sum_w h[b,w]U[w,d] / 64
//              dlogp[b]= -sum_w (1-h^2)wu[w] / 64
//   Output: concat(dz_dt.flatten(), dlogp.flatten())
// ---------------------------------------------------------------------------

#define D       64
#define HID     512
#define WIDTH   64
#define BATCH   524288
#define BLOCK_P (WIDTH * D)     // 4096
#define NP      (3 * BLOCK_P + WIDTH)  // 12352

// device scratch (no allocations allowed)
__device__ float g_p2[HID];
__device__ float g_p3[NP];

// ---------------- packed f32x2 helpers (Blackwell) -------------------------
typedef unsigned long long f32x2_t;

__device__ __forceinline__ f32x2_t f2pack(float lo, float hi) {
    f32x2_t r;
    asm("mov.b64 %0, {%1, %2};" : "=l"(r) : "f"(lo), "f"(hi));
    return r;
}
__device__ __forceinline__ void f2unpack(f32x2_t v, float& lo, float& hi) {
    asm("mov.b64 {%0, %1}, %2;" : "=f"(lo), "=f"(hi) : "l"(v));
}
__device__ __forceinline__ f32x2_t f2fma(f32x2_t a, f32x2_t b, f32x2_t c) {
    f32x2_t r;
    asm("fma.rn.f32x2 %0, %1, %2, %3;" : "=l"(r) : "l"(a), "l"(b), "l"(c));
    return r;
}

// accurate-enough tanh: 1 - 2/(exp(2x)+1); abs err ~1e-6
__device__ __forceinline__ float fast_tanh(float x) {
    float e = __expf(2.0f * x);
    return 1.0f - 2.0f / (e + 1.0f);
}

// ---------------- hypernet stage 1: p1, p2 ---------------------------------
__global__ void hyper1_kernel(const float* __restrict__ t,
                              const float* __restrict__ W1,
                              const float* __restrict__ b1,
                              const float* __restrict__ W2,
                              const float* __restrict__ b2) {
    __shared__ float s1[HID];
    int i = threadIdx.x;
    float tv = t[0];
    s1[i] = tanhf(tv * W1[i] + b1[i]);
    __syncthreads();
    float acc = 0.0f;
#pragma unroll 8
    for (int k = 0; k < HID; k++)
        acc = fmaf(s1[k], W2[k * HID + i], acc);
    g_p2[i] = tanhf(acc + b2[i]);
}

// ---------------- hypernet stage 2: p3 = p2 @ W3 + b3 ----------------------
__global__ void hyper2_kernel(const float* __restrict__ W3,
                              const float* __restrict__ b3) {
    __shared__ float s2[HID];
    for (int k = threadIdx.x; k < HID; k += blockDim.x)
        s2[k] = g_p2[k];
    __syncthreads();
    int j = blockIdx.x * blockDim.x + threadIdx.x;
    if (j >= NP) return;
    float acc = b3[j];
#pragma unroll 8
    for (int k = 0; k < HID; k++)
        acc = fmaf(s2[k], W3[(size_t)k * NP + j], acc);
    g_p3[j] = acc;
}

// ---------------- main batch kernel -----------------------------------------
// one thread per batch row; z/dz in registers as f32x2; W,U in smem.
__global__ __launch_bounds__(128, 3)
void cnf_main_kernel(const float* __restrict__ z, float* __restrict__ out) {
    __shared__ __align__(16) float sW[BLOCK_P];
    __shared__ __align__(16) float sU[BLOCK_P];
    __shared__ float sB[WIDTH];
    __shared__ float swu[WIDTH];

    // build per-time params in smem (sigmoid gating applied here)
    for (int i = threadIdx.x; i < BLOCK_P; i += 128) {
        float w = g_p3[i];
        float u = g_p3[BLOCK_P + i];
        float g = g_p3[2 * BLOCK_P + i];
        float sg = 1.0f / (1.0f + __expf(-g));
        sW[i] = w;
        sU[i] = u * sg;
    }
    if (threadIdx.x < WIDTH)
        sB[threadIdx.x] = g_p3[3 * BLOCK_P + threadIdx.x];
    __syncthreads();
    if (threadIdx.x < WIDTH) {
        int w = threadIdx.x;
        float acc = 0.0f;
#pragma unroll
        for (int d = 0; d < D; d++)
            acc = fmaf(sW[w * D + d], sU[w * D + d], acc);
        swu[w] = acc;
    }
    __syncthreads();

    size_t row = (size_t)blockIdx.x * 128 + threadIdx.x;

    // load z row (64 floats) into 32 packed regs
    const float4* zr = (const float4*)(z + row * D);
    f32x2_t z2[32];
#pragma unroll
    for (int i = 0; i < 16; i++) {
        float4 v = zr[i];
        z2[2 * i]     = f2pack(v.x, v.y);
        z2[2 * i + 1] = f2pack(v.z, v.w);
    }

    f32x2_t dz[32];
#pragma unroll
    for (int i = 0; i < 32; i++) dz[i] = 0ull;

    const f32x2_t* sW2 = (const f32x2_t*)sW;
    const f32x2_t* sU2 = (const f32x2_t*)sU;

    float tr = 0.0f;
    for (int w = 0; w < WIDTH; w++) {
        // h = tanh(z . W[w] + B[w]) ; 4 accumulators for ILP
        f32x2_t a0 = 0ull, a1 = 0ull, a2 = 0ull, a3 = 0ull;
        const f32x2_t* wr = sW2 + w * 32;
#pragma unroll
        for (int i = 0; i < 32; i += 4) {
            a0 = f2fma(z2[i],     wr[i],     a0);
            a1 = f2fma(z2[i + 1], wr[i + 1], a1);
            a2 = f2fma(z2[i + 2], wr[i + 2], a2);
            a3 = f2fma(z2[i + 3], wr[i + 3], a3);
        }
        float x0, x1, y0, y1, u0, u1, v0, v1;
        f2unpack(a0, x0, x1);
        f2unpack(a1, y0, y1);
        f2unpack(a2, u0, u1);
        f2unpack(a3, v0, v1);
        float s = ((x0 + x1) + (y0 + y1)) + ((u0 + u1) + (v0 + v1)) + sB[w];
        float h = fast_tanh(s);

        // dz += h * U[w, :]
        f32x2_t hh = f2pack(h, h);
        const f32x2_t* ur = sU2 + w * 32;
#pragma unroll
        for (int i = 0; i < 32; i++)
            dz[i] = f2fma(hh, ur[i], dz[i]);

        // trace accumulation
        tr = fmaf(1.0f - h * h, swu[w], tr);
    }

    // write dz/64 and -tr/64
    const float inv = 1.0f / (float)WIDTH;
    float4* op = (float4*)(out + row * D);
#pragma unroll
    for (int i = 0; i < 16; i++) {
        float a, b, c, d;
        f2unpack(dz[2 * i], a, b);
        f2unpack(dz[2 * i + 1], c, d);
        op[i] = make_float4(a * inv, b * inv, c * inv, d * inv);
    }
    out[(size_t)BATCH * D + row] = -tr * inv;
}

// ---------------------------------------------------------------------------
extern "C" void kernel_launch(void* const* d_in, const int* in_sizes, int n_in,
                              void* d_out, int out_size) {
    const float* t   = (const float*)d_in[0];
    const float* z   = (const float*)d_in[1];
    // d_in[2] = logp_z (unused by the math)
    const float* W1  = (const float*)d_in[3];
    const float* b1  = (const float*)d_in[4];
    const float* W2  = (const float*)d_in[5];
    const float* b2  = (const float*)d_in[6];
    const float* W3  = (const float*)d_in[7];
    const float* b3  = (const float*)d_in[8];
    float* out = (float*)d_out;

    hyper1_kernel<<<1, HID>>>(t, W1, b1, W2, b2);
    hyper2_kernel<<<(NP + 127) / 128, 128>>>(W3, b3);
    cnf_main_kernel<<<BATCH / 128, 128>>>(z, out);
}

// round 3
// speedup vs baseline: 3.5723x; 3.5723x over previous
#include <cuda_runtime.h>
#include <cuda_bf16.h>
#include <cstdint>

// ---------------------------------------------------------------------------
// CNF_59133109731627 — warp-level HMMA (split-bf16, mma.sync m16n8k16) version
//   hyper1: p2 = tanh(tanh(t*W1+b1) @ W2 + b2)
//   hyper2: p3 = p2 @ W3 + b3
//   hyper3: prep W (w,d), gated U^T (d,w), B, wu; bf16 hi/lo splits
//   main:   per warp = 32 batch rows:
//     S  = z_hi*W_hi + z_lo*W_hi + z_hi*W_lo         (mma.sync bf16, f32 acc)
//     h  = tanh(S+B); tr = sum (1-h^2) wu            (register-local)
//     dz = (h_hi*Ut_hi + h_lo*Ut_hi + h_hi*Ut_lo)/64
// ---------------------------------------------------------------------------

#define D_      64
#define HID     512
#define WIDTH   64
#define BATCH   524288
#define BLOCK_P (WIDTH * D_)            // 4096
#define NP      (3 * BLOCK_P + WIDTH)   // 12352
#define SROW    144                     // padded smem row pitch (bytes)

// ---------------- device scratch ---------------------------------------------
__device__ float g_p2[HID];
__device__ float g_p3[NP];
__device__ __align__(16) __nv_bfloat16 g_whi[BLOCK_P];   // W  [w][d] hi
__device__ __align__(16) __nv_bfloat16 g_wlo[BLOCK_P];   // W  [w][d] lo
__device__ __align__(16) __nv_bfloat16 g_uthi[BLOCK_P];  // U^T[d][w] hi (gated)
__device__ __align__(16) __nv_bfloat16 g_utlo[BLOCK_P];  // U^T[d][w] lo
__device__ float g_B[WIDTH];
__device__ float g_wu[WIDTH];

// ---------------- helpers -----------------------------------------------------
__device__ __forceinline__ float fast_tanh(float x) {
    float e = __expf(2.0f * x);
    return 1.0f - __fdividef(2.0f, e + 1.0f);
}

__device__ __forceinline__ void mma_bf16(float d[4], const uint32_t a[4],
                                         const uint32_t b[2], const float c[4]) {
    asm volatile(
        "mma.sync.aligned.m16n8k16.row.col.f32.bf16.bf16.f32 "
        "{%0,%1,%2,%3}, {%4,%5,%6,%7}, {%8,%9}, {%10,%11,%12,%13};\n"
        : "=f"(d[0]), "=f"(d[1]), "=f"(d[2]), "=f"(d[3])
        : "r"(a[0]), "r"(a[1]), "r"(a[2]), "r"(a[3]),
          "r"(b[0]), "r"(b[1]),
          "f"(c[0]), "f"(c[1]), "f"(c[2]), "f"(c[3]));
}

// split a float2 into packed bf16x2 hi and lo parts
__device__ __forceinline__ void split2(float2 v, uint32_t& hi, uint32_t& lo) {
    __nv_bfloat162 h = __float22bfloat162_rn(v);
    hi = *(uint32_t*)&h;
    float2 r;
    r.x = v.x - __bfloat162float(h.x);
    r.y = v.y - __bfloat162float(h.y);
    __nv_bfloat162 l = __float22bfloat162_rn(r);
    lo = *(uint32_t*)&l;
}

// ---------------- hypernet ----------------------------------------------------
__global__ void hyper1_kernel(const float* __restrict__ t,
                              const float* __restrict__ W1,
                              const float* __restrict__ b1,
                              const float* __restrict__ W2,
                              const float* __restrict__ b2) {
    __shared__ float p1[HID];
    __shared__ float red[8];
    int j = blockIdx.x;
    int tid = threadIdx.x;
    float tv = t[0];
    for (int k = tid; k < HID; k += 256)
        p1[k] = tanhf(tv * W1[k] + b1[k]);
    __syncthreads();
    float acc = p1[tid] * W2[(size_t)tid * HID + j]
              + p1[tid + 256] * W2[(size_t)(tid + 256) * HID + j];
#pragma unroll
    for (int off = 16; off > 0; off >>= 1)
        acc += __shfl_xor_sync(0xFFFFFFFFu, acc, off);
    if ((tid & 31) == 0) red[tid >> 5] = acc;
    __syncthreads();
    if (tid == 0) {
        float s = b2[j];
#pragma unroll
        for (int w = 0; w < 8; w++) s += red[w];
        g_p2[j] = tanhf(s);
    }
}

__global__ void hyper2_kernel(const float* __restrict__ W3,
                              const float* __restrict__ b3) {
    __shared__ float s2[HID];
    for (int k = threadIdx.x; k < HID; k += blockDim.x)
        s2[k] = g_p2[k];
    __syncthreads();
    int j = blockIdx.x * blockDim.x + threadIdx.x;
    if (j >= NP) return;
    float acc = b3[j];
#pragma unroll 8
    for (int k = 0; k < HID; k++)
        acc = fmaf(s2[k], W3[(size_t)k * NP + j], acc);
    g_p3[j] = acc;
}

// prep: gate U, transpose, bf16 split, wu, B. grid=64 (w), block=64 (d)
__global__ void hyper3_kernel() {
    __shared__ float prod[WIDTH];
    int w = blockIdx.x, d = threadIdx.x;
    int idx = w * D_ + d;
    float Wv = g_p3[idx];
    float gv = g_p3[2 * BLOCK_P + idx];
    float Uv = g_p3[BLOCK_P + idx] * (1.0f / (1.0f + __expf(-gv)));

    __nv_bfloat16 wh = __float2bfloat16_rn(Wv);
    g_whi[idx] = wh;
    g_wlo[idx] = __float2bfloat16_rn(Wv - __bfloat162float(wh));
    __nv_bfloat16 uh = __float2bfloat16_rn(Uv);
    g_uthi[d * WIDTH + w] = uh;
    g_utlo[d * WIDTH + w] = __float2bfloat16_rn(Uv - __bfloat162float(uh));

    prod[d] = Wv * Uv;
    __syncthreads();
    if (d == 0) {
        float s = 0.0f;
#pragma unroll
        for (int k = 0; k < D_; k++) s += prod[k];
        g_wu[w] = s;
    }
    if (w == 0) g_B[d] = g_p3[3 * BLOCK_P + d];
}

// ---------------- main batch kernel -------------------------------------------
// CTA = 128 threads = 4 warps; warp = 32 batch rows; grid = 4096.
// B-frag smem pitch 144B => LDS bank = (4g + t) mod 32, conflict-free.
__global__ __launch_bounds__(128)
void cnf_mma_kernel(const float* __restrict__ z, float* __restrict__ out) {
    __shared__ __align__(16) uint8_t sWhi[WIDTH * SROW];
    __shared__ __align__(16) uint8_t sWlo[WIDTH * SROW];
    __shared__ __align__(16) uint8_t sUthi[WIDTH * SROW];
    __shared__ __align__(16) uint8_t sUtlo[WIDTH * SROW];
    __shared__ float sB[WIDTH];
    __shared__ float swu[WIDTH];

    const int tid = threadIdx.x;

    // stage weights (row-major 128B rows -> 144B pitch smem)
    {
        const uint4* s0 = (const uint4*)g_whi;
        const uint4* s1 = (const uint4*)g_wlo;
        const uint4* s2 = (const uint4*)g_uthi;
        const uint4* s3 = (const uint4*)g_utlo;
#pragma unroll
        for (int i = tid; i < 512; i += 128) {
            int r = i >> 3, c = i & 7;
            int dst = r * SROW + c * 16;
            *(uint4*)(sWhi + dst)  = s0[i];
            *(uint4*)(sWlo + dst)  = s1[i];
            *(uint4*)(sUthi + dst) = s2[i];
            *(uint4*)(sUtlo + dst) = s3[i];
        }
        if (tid < WIDTH) { sB[tid] = g_B[tid]; swu[tid] = g_wu[tid]; }
    }
    __syncthreads();

    const int lane = tid & 31;
    const int warp = tid >> 5;
    const int g = lane >> 2;   // group id  (row within 8)
    const int t = lane & 3;    // thread in group (col pair)

    const size_t rowbase = (size_t)blockIdx.x * 128 + (size_t)warp * 32;

    // ---- load z -> hi/lo A fragments (2 m-tiles x 4 k-tiles) ----------------
    uint32_t zh[2][4][4], zl[2][4][4];
#pragma unroll
    for (int m = 0; m < 2; m++) {
        const float2* zr0 = (const float2*)(z + (rowbase + 16 * m + g) * D_);
        const float2* zr1 = (const float2*)(z + (rowbase + 16 * m + g + 8) * D_);
#pragma unroll
        for (int kt = 0; kt < 4; kt++) {
            float2 v00 = zr0[8 * kt + t];
            float2 v10 = zr1[8 * kt + t];
            float2 v01 = zr0[8 * kt + 4 + t];
            float2 v11 = zr1[8 * kt + 4 + t];
            split2(v00, zh[m][kt][0], zl[m][kt][0]);
            split2(v10, zh[m][kt][1], zl[m][kt][1]);
            split2(v01, zh[m][kt][2], zl[m][kt][2]);
            split2(v11, zh[m][kt][3], zl[m][kt][3]);
        }
    }

    // ---- GEMM1: S = zhi*Whi + zlo*Whi + zhi*Wlo ------------------------------
    float S[2][8][4];
#pragma unroll
    for (int m = 0; m < 2; m++)
#pragma unroll
        for (int n = 0; n < 8; n++)
#pragma unroll
            for (int i = 0; i < 4; i++) S[m][n][i] = 0.0f;

#pragma unroll
    for (int n = 0; n < 8; n++) {
        uint32_t bh[4][2], bl[4][2];
        const uint8_t* ph = sWhi + (8 * n + g) * SROW + 4 * t;
        const uint8_t* pl = sWlo + (8 * n + g) * SROW + 4 * t;
#pragma unroll
        for (int kt = 0; kt < 4; kt++) {
            bh[kt][0] = *(const uint32_t*)(ph + 32 * kt);
            bh[kt][1] = *(const uint32_t*)(ph + 32 * kt + 16);
            bl[kt][0] = *(const uint32_t*)(pl + 32 * kt);
            bl[kt][1] = *(const uint32_t*)(pl + 32 * kt + 16);
        }
#pragma unroll
        for (int kt = 0; kt < 4; kt++) {
            mma_bf16(S[0][n], zh[0][kt], bh[kt], S[0][n]);
            mma_bf16(S[1][n], zh[1][kt], bh[kt], S[1][n]);
            mma_bf16(S[0][n], zl[0][kt], bh[kt], S[0][n]);
            mma_bf16(S[1][n], zl[1][kt], bh[kt], S[1][n]);
            mma_bf16(S[0][n], zh[0][kt], bl[kt], S[0][n]);
            mma_bf16(S[1][n], zh[1][kt], bl[kt], S[1][n]);
        }
    }

    // ---- epilogue 1: h = tanh(S+B), trace, repack into GEMM2 A frags ---------
    uint32_t hh[2][4][4], hl[2][4][4];
    float tr[2][2] = {{0.0f, 0.0f}, {0.0f, 0.0f}};
#pragma unroll
    for (int m = 0; m < 2; m++) {
#pragma unroll
        for (int n = 0; n < 8; n++) {
            float2 bb = *(const float2*)&sB[8 * n + 2 * t];
            float2 ww = *(const float2*)&swu[8 * n + 2 * t];
            float h0 = fast_tanh(S[m][n][0] + bb.x);
            float h1 = fast_tanh(S[m][n][1] + bb.y);
            float h2 = fast_tanh(S[m][n][2] + bb.x);
            float h3 = fast_tanh(S[m][n][3] + bb.y);
            tr[m][0] = fmaf(1.0f - h0 * h0, ww.x, tr[m][0]);
            tr[m][0] = fmaf(1.0f - h1 * h1, ww.y, tr[m][0]);
            tr[m][1] = fmaf(1.0f - h2 * h2, ww.x, tr[m][1]);
            tr[m][1] = fmaf(1.0f - h3 * h3, ww.y, tr[m][1]);
            int kt = n >> 1;
            int o = (n & 1) ? 2 : 0;   // regs 0,1 from even n-tile; 2,3 from odd
            split2(make_float2(h0, h1), hh[m][kt][o],     hl[m][kt][o]);
            split2(make_float2(h2, h3), hh[m][kt][o + 1], hl[m][kt][o + 1]);
        }
    }

    // ---- GEMM2: dz = hhi*Uthi + hlo*Uthi + hhi*Utlo --------------------------
    float DZ[2][8][4];
#pragma unroll
    for (int m = 0; m < 2; m++)
#pragma unroll
        for (int n = 0; n < 8; n++)
#pragma unroll
            for (int i = 0; i < 4; i++) DZ[m][n][i] = 0.0f;

#pragma unroll
    for (int n = 0; n < 8; n++) {
        uint32_t bh[4][2], bl[4][2];
        const uint8_t* ph = sUthi + (8 * n + g) * SROW + 4 * t;
        const uint8_t* pl = sUtlo + (8 * n + g) * SROW + 4 * t;
#pragma unroll
        for (int kt = 0; kt < 4; kt++) {
            bh[kt][0] = *(const uint32_t*)(ph + 32 * kt);
            bh[kt][1] = *(const uint32_t*)(ph + 32 * kt + 16);
            bl[kt][0] = *(const uint32_t*)(pl + 32 * kt);
            bl[kt][1] = *(const uint32_t*)(pl + 32 * kt + 16);
        }
#pragma unroll
        for (int kt = 0; kt < 4; kt++) {
            mma_bf16(DZ[0][n], hh[0][kt], bh[kt], DZ[0][n]);
            mma_bf16(DZ[1][n], hh[1][kt], bh[kt], DZ[1][n]);
            mma_bf16(DZ[0][n], hl[0][kt], bh[kt], DZ[0][n]);
            mma_bf16(DZ[1][n], hl[1][kt], bh[kt], DZ[1][n]);
            mma_bf16(DZ[0][n], hh[0][kt], bl[kt], DZ[0][n]);
            mma_bf16(DZ[1][n], hh[1][kt], bl[kt], DZ[1][n]);
        }
    }

    // ---- write dz/64 ----------------------------------------------------------
    const float inv = 1.0f / (float)WIDTH;
#pragma unroll
    for (int m = 0; m < 2; m++) {
        size_t r0 = rowbase + 16 * m + g;
#pragma unroll
        for (int n = 0; n < 8; n++) {
            int col = 8 * n + 2 * t;
            *(float2*)(out + r0 * D_ + col) =
                make_float2(DZ[m][n][0] * inv, DZ[m][n][1] * inv);
            *(float2*)(out + (r0 + 8) * D_ + col) =
                make_float2(DZ[m][n][2] * inv, DZ[m][n][3] * inv);
        }
    }

    // ---- trace: reduce over col-groups, write -tr/64 ---------------------------
#pragma unroll
    for (int m = 0; m < 2; m++)
#pragma unroll
        for (int rh = 0; rh < 2; rh++) {
            float v = tr[m][rh];
            v += __shfl_xor_sync(0xFFFFFFFFu, v, 1);
            v += __shfl_xor_sync(0xFFFFFFFFu, v, 2);
            tr[m][rh] = v;
        }
    {
        float trv = (t == 0) ? tr[0][0] : (t == 1) ? tr[0][1]
                  : (t == 2) ? tr[1][0] : tr[1][1];
        size_t row = rowbase + (size_t)g + 8 * (t & 1) + 16 * (t >> 1);
        out[(size_t)BATCH * D_ + row] = -trv * inv;
    }
}

// ---------------------------------------------------------------------------
extern "C" void kernel_launch(void* const* d_in, const int* in_sizes, int n_in,
                              void* d_out, int out_size) {
    const float* t  = (const float*)d_in[0];
    const float* z  = (const float*)d_in[1];
    const float* W1 = (const float*)d_in[3];
    const float* b1 = (const float*)d_in[4];
    const float* W2 = (const float*)d_in[5];
    const float* b2 = (const float*)d_in[6];
    const float* W3 = (const float*)d_in[7];
    const float* b3 = (const float*)d_in[8];
    float* out = (float*)d_out;

    hyper1_kernel<<<HID, 256>>>(t, W1, b1, W2, b2);
    hyper2_kernel<<<(NP + 127) / 128, 128>>>(W3, b3);
    hyper3_kernel<<<WIDTH, D_>>>();
    cnf_mma_kernel<<<BATCH / 128, 128>>>(z, out);
}

// round 4
// speedup vs baseline: 4.0661x; 1.1383x over previous
#include <cuda_runtime.h>
#include <cuda_bf16.h>
#include <cstdint>

// ---------------------------------------------------------------------------
// CNF_59133109731627 — split-bf16 mma.sync m16n8k16, round 4
//  - hyperA: p2 = tanh(tanh(t*W1+b1) @ W2 + b2)   (fused, k-split, coalesced)
//  - hyperB: p3 = p2 @ W3 + b3                    (4-way k-split)
//  - hyper3: gate U, transpose, bf16 hi/lo splits, wu, B
//  - main:   per warp = 32 rows, m-tiles sequential, ldmatrix B-frags,
//            4 batch tiles per CTA
// ---------------------------------------------------------------------------

#define D_      64
#define HID     512
#define WIDTH   64
#define BATCH   524288
#define BLOCK_P (WIDTH * D_)            // 4096
#define NP      (3 * BLOCK_P + WIDTH)   // 12352
#define SROW    144                     // padded smem row pitch (bytes)
#define TILES   4                       // batch tiles (128 rows) per CTA
#define GRID    (BATCH / (128 * TILES)) // 1024

// ---------------- device scratch ---------------------------------------------
__device__ float g_p2[HID];
__device__ float g_p3[NP];
__device__ __align__(16) __nv_bfloat16 g_whi[BLOCK_P];   // W  [w][d] hi
__device__ __align__(16) __nv_bfloat16 g_wlo[BLOCK_P];   // W  [w][d] lo
__device__ __align__(16) __nv_bfloat16 g_uthi[BLOCK_P];  // U^T[d][w] hi (gated)
__device__ __align__(16) __nv_bfloat16 g_utlo[BLOCK_P];  // U^T[d][w] lo
__device__ float g_B[WIDTH];
__device__ float g_wu[WIDTH];

// ---------------- helpers -----------------------------------------------------
__device__ __forceinline__ float fast_tanh(float x) {
    float e = __expf(2.0f * x);
    return 1.0f - __fdividef(2.0f, e + 1.0f);
}

__device__ __forceinline__ uint32_t smem_u32(const void* p) {
    uint32_t a;
    asm("{ .reg .u64 t; cvta.to.shared.u64 t, %1; cvt.u32.u64 %0, t; }"
        : "=r"(a) : "l"(p));
    return a;
}

__device__ __forceinline__ void mma_bf16(float d[4], const uint32_t a[4],
                                         const uint32_t b[2], const float c[4]) {
    asm volatile(
        "mma.sync.aligned.m16n8k16.row.col.f32.bf16.bf16.f32 "
        "{%0,%1,%2,%3}, {%4,%5,%6,%7}, {%8,%9}, {%10,%11,%12,%13};\n"
        : "=f"(d[0]), "=f"(d[1]), "=f"(d[2]), "=f"(d[3])
        : "r"(a[0]), "r"(a[1]), "r"(a[2]), "r"(a[3]),
          "r"(b[0]), "r"(b[1]),
          "f"(c[0]), "f"(c[1]), "f"(c[2]), "f"(c[3]));
}

__device__ __forceinline__ void ldsm_x4(uint32_t r[4], uint32_t saddr) {
    asm volatile(
        "ldmatrix.sync.aligned.m8n8.x4.shared.b16 {%0,%1,%2,%3}, [%4];"
        : "=r"(r[0]), "=r"(r[1]), "=r"(r[2]), "=r"(r[3]) : "r"(saddr));
}

__device__ __forceinline__ void split2(float2 v, uint32_t& hi, uint32_t& lo) {
    __nv_bfloat162 h = __float22bfloat162_rn(v);
    hi = *(uint32_t*)&h;
    float2 r;
    r.x = v.x - __bfloat162float(h.x);
    r.y = v.y - __bfloat162float(h.y);
    __nv_bfloat162 l = __float22bfloat162_rn(r);
    lo = *(uint32_t*)&l;
}

// ---------------- hyperA: p2 = tanh(tanh(t*W1+b1) @ W2 + b2) -------------------
// grid 16 x 256: block computes 32 outputs, 8-way k-split, coalesced W2 rows.
__global__ void hyperA_kernel(const float* __restrict__ t,
                              const float* __restrict__ W1,
                              const float* __restrict__ b1,
                              const float* __restrict__ W2,
                              const float* __restrict__ b2) {
    __shared__ float p1[HID];
    __shared__ float red[8][32];
    const int tid = threadIdx.x;
    float tv = t[0];
    for (int k = tid; k < HID; k += 256)
        p1[k] = tanhf(tv * W1[k] + b1[k]);
    __syncthreads();
    const int x = tid & 31, y = tid >> 5;
    const int j = blockIdx.x * 32 + x;
    float acc = 0.0f;
#pragma unroll 8
    for (int i = 0; i < 64; i++) {
        int k = y + 8 * i;
        acc = fmaf(p1[k], W2[(size_t)k * HID + j], acc);
    }
    red[y][x] = acc;
    __syncthreads();
    if (tid < 32) {
        float s = b2[j];
#pragma unroll
        for (int yy = 0; yy < 8; yy++) s += red[yy][tid];
        g_p2[j] = tanhf(s);
    }
}

// ---------------- hyperB: p3 = p2 @ W3 + b3 ------------------------------------
// grid 97 x 512: 128 outputs per block, 4-way k-split.
__global__ void hyperB_kernel(const float* __restrict__ W3,
                              const float* __restrict__ b3) {
    __shared__ float s2[HID];
    __shared__ float red[4][128];
    const int tid = threadIdx.x;
    if (tid < HID) s2[tid] = g_p2[tid];
    __syncthreads();
    const int x = tid & 127, y = tid >> 7;
    const int j = blockIdx.x * 128 + x;
    const bool ok = j < NP;
    float acc = 0.0f;
    if (ok) {
#pragma unroll 8
        for (int i = 0; i < 128; i++) {
            int k = y + 4 * i;
            acc = fmaf(s2[k], W3[(size_t)k * NP + j], acc);
        }
    }
    red[y][x] = acc;
    __syncthreads();
    if (y == 0 && ok)
        g_p3[j] = red[0][x] + red[1][x] + red[2][x] + red[3][x] + b3[j];
}

// ---------------- hyper3: param prep ------------------------------------------
__global__ void hyper3_kernel() {
    __shared__ float prod[WIDTH];
    int w = blockIdx.x, d = threadIdx.x;
    int idx = w * D_ + d;
    float Wv = g_p3[idx];
    float gv = g_p3[2 * BLOCK_P + idx];
    float Uv = g_p3[BLOCK_P + idx] * (1.0f / (1.0f + __expf(-gv)));

    __nv_bfloat16 wh = __float2bfloat16_rn(Wv);
    g_whi[idx] = wh;
    g_wlo[idx] = __float2bfloat16_rn(Wv - __bfloat162float(wh));
    __nv_bfloat16 uh = __float2bfloat16_rn(Uv);
    g_uthi[d * WIDTH + w] = uh;
    g_utlo[d * WIDTH + w] = __float2bfloat16_rn(Uv - __bfloat162float(uh));

    prod[d] = Wv * Uv;
    __syncthreads();
    if (d == 0) {
        float s = 0.0f;
#pragma unroll
        for (int k = 0; k < D_; k++) s += prod[k];
        g_wu[w] = s;
    }
    if (w == 0) g_B[d] = g_p3[3 * BLOCK_P + d];
}

// ---------------- main batch kernel --------------------------------------------
__global__ __launch_bounds__(128, 4)
void cnf_mma_kernel(const float* __restrict__ z, float* __restrict__ out) {
    __shared__ __align__(16) uint8_t sWhi[WIDTH * SROW];
    __shared__ __align__(16) uint8_t sWlo[WIDTH * SROW];
    __shared__ __align__(16) uint8_t sUthi[WIDTH * SROW];
    __shared__ __align__(16) uint8_t sUtlo[WIDTH * SROW];
    __shared__ float sB[WIDTH];
    __shared__ float swu[WIDTH];

    const int tid = threadIdx.x;

    // stage weights (128B global rows -> 144B pitch smem)
    {
        const uint4* s0 = (const uint4*)g_whi;
        const uint4* s1 = (const uint4*)g_wlo;
        const uint4* s2 = (const uint4*)g_uthi;
        const uint4* s3 = (const uint4*)g_utlo;
#pragma unroll
        for (int i = tid; i < 512; i += 128) {
            int r = i >> 3, c = i & 7;
            int dst = r * SROW + c * 16;
            *(uint4*)(sWhi + dst)  = s0[i];
            *(uint4*)(sWlo + dst)  = s1[i];
            *(uint4*)(sUthi + dst) = s2[i];
            *(uint4*)(sUtlo + dst) = s3[i];
        }
        if (tid < WIDTH) { sB[tid] = g_B[tid]; swu[tid] = g_wu[tid]; }
    }
    __syncthreads();

    const int lane = tid & 31;
    const int warp = tid >> 5;
    const int g = lane >> 2;     // group (row within 8)
    const int t = lane & 3;      // thread in group
    const int rrow = lane & 7;   // ldmatrix row provider
    const int qq = lane >> 3;    // ldmatrix matrix id

    const uint32_t baseWhi  = smem_u32(sWhi);
    const uint32_t baseWlo  = smem_u32(sWlo);
    const uint32_t baseUthi = smem_u32(sUthi);
    const uint32_t baseUtlo = smem_u32(sUtlo);
    const float inv = 1.0f / (float)WIDTH;

    for (int tile = 0; tile < TILES; tile++) {
        const size_t rowbase = ((size_t)blockIdx.x * TILES + tile) * 128
                             + (size_t)warp * 32;
#pragma unroll
        for (int m = 0; m < 2; m++) {
            const size_t r0 = rowbase + 16 * m + g;

            // ---- load z rows r0, r0+8 -> hi/lo A-frags --------------------
            uint32_t zh[4][4], zl[4][4];
            {
                const float2* zr0 = (const float2*)(z + r0 * D_);
                const float2* zr1 = (const float2*)(z + (r0 + 8) * D_);
                float2 v[4][4];
#pragma unroll
                for (int kt = 0; kt < 4; kt++) {
                    v[kt][0] = zr0[8 * kt + t];
                    v[kt][1] = zr1[8 * kt + t];
                    v[kt][2] = zr0[8 * kt + 4 + t];
                    v[kt][3] = zr1[8 * kt + 4 + t];
                }
#pragma unroll
                for (int kt = 0; kt < 4; kt++)
#pragma unroll
                    for (int i = 0; i < 4; i++)
                        split2(v[kt][i], zh[kt][i], zl[kt][i]);
            }

            // ---- GEMM1: S = zh*Wh + zl*Wh + zh*Wl --------------------------
            float S[8][4];
#pragma unroll
            for (int n = 0; n < 8; n++) {
                const uint32_t off = (uint32_t)((8 * n + rrow) * SROW + qq * 16);
                uint32_t bh[8], bl[8];
                ldsm_x4(&bh[0], baseWhi + off);
                ldsm_x4(&bh[4], baseWhi + off + 64);
                ldsm_x4(&bl[0], baseWlo + off);
                ldsm_x4(&bl[4], baseWlo + off + 64);
#pragma unroll
                for (int i = 0; i < 4; i++) S[n][i] = 0.0f;
#pragma unroll
                for (int kt = 0; kt < 4; kt++) {
                    mma_bf16(S[n], zh[kt], &bh[2 * kt], S[n]);
                    mma_bf16(S[n], zl[kt], &bh[2 * kt], S[n]);
                    mma_bf16(S[n], zh[kt], &bl[2 * kt], S[n]);
                }
            }

            // ---- epilogue: h = tanh(S+B), trace, repack A2 frags -----------
            uint32_t hh[4][4], hl[4][4];
            float tr0 = 0.0f, tr1 = 0.0f;
#pragma unroll
            for (int n = 0; n < 8; n++) {
                float2 bb = *(const float2*)&sB[8 * n + 2 * t];
                float2 ww = *(const float2*)&swu[8 * n + 2 * t];
                float h0 = fast_tanh(S[n][0] + bb.x);
                float h1 = fast_tanh(S[n][1] + bb.y);
                float h2 = fast_tanh(S[n][2] + bb.x);
                float h3 = fast_tanh(S[n][3] + bb.y);
                tr0 = fmaf(1.0f - h0 * h0, ww.x, tr0);
                tr0 = fmaf(1.0f - h1 * h1, ww.y, tr0);
                tr1 = fmaf(1.0f - h2 * h2, ww.x, tr1);
                tr1 = fmaf(1.0f - h3 * h3, ww.y, tr1);
                int kt = n >> 1;
                int o = (n & 1) ? 2 : 0;
                split2(make_float2(h0, h1), hh[kt][o],     hl[kt][o]);
                split2(make_float2(h2, h3), hh[kt][o + 1], hl[kt][o + 1]);
            }

            // ---- GEMM2: DZ = hh*Uth + hl*Uth + hh*Utl -----------------------
            float DZ[8][4];
#pragma unroll
            for (int n = 0; n < 8; n++) {
                const uint32_t off = (uint32_t)((8 * n + rrow) * SROW + qq * 16);
                uint32_t bh[8], bl[8];
                ldsm_x4(&bh[0], baseUthi + off);
                ldsm_x4(&bh[4], baseUthi + off + 64);
                ldsm_x4(&bl[0], baseUtlo + off);
                ldsm_x4(&bl[4], baseUtlo + off + 64);
#pragma unroll
                for (int i = 0; i < 4; i++) DZ[n][i] = 0.0f;
#pragma unroll
                for (int kt = 0; kt < 4; kt++) {
                    mma_bf16(DZ[n], hh[kt], &bh[2 * kt], DZ[n]);
                    mma_bf16(DZ[n], hl[kt], &bh[2 * kt], DZ[n]);
                    mma_bf16(DZ[n], hh[kt], &bl[2 * kt], DZ[n]);
                }
            }

            // ---- store dz/64 -------------------------------------------------
#pragma unroll
            for (int n = 0; n < 8; n++) {
                int col = 8 * n + 2 * t;
                *(float2*)(out + r0 * D_ + col) =
                    make_float2(DZ[n][0] * inv, DZ[n][1] * inv);
                *(float2*)(out + (r0 + 8) * D_ + col) =
                    make_float2(DZ[n][2] * inv, DZ[n][3] * inv);
            }

            // ---- trace: reduce over t, write -tr/64 --------------------------
            tr0 += __shfl_xor_sync(0xFFFFFFFFu, tr0, 1);
            tr0 += __shfl_xor_sync(0xFFFFFFFFu, tr0, 2);
            tr1 += __shfl_xor_sync(0xFFFFFFFFu, tr1, 1);
            tr1 += __shfl_xor_sync(0xFFFFFFFFu, tr1, 2);
            if (t == 0) out[(size_t)BATCH * D_ + r0] = -tr0 * inv;
            if (t == 1) out[(size_t)BATCH * D_ + r0 + 8] = -tr1 * inv;
        }
    }
}

// ---------------------------------------------------------------------------
extern "C" void kernel_launch(void* const* d_in, const int* in_sizes, int n_in,
                              void* d_out, int out_size) {
    const float* t  = (const float*)d_in[0];
    const float* z  = (const float*)d_in[1];
    const float* W1 = (const float*)d_in[3];
    const float* b1 = (const float*)d_in[4];
    const float* W2 = (const float*)d_in[5];
    const float* b2 = (const float*)d_in[6];
    const float* W3 = (const float*)d_in[7];
    const float* b3 = (const float*)d_in[8];
    float* out = (float*)d_out;

    hyperA_kernel<<<16, 256>>>(t, W1, b1, W2, b2);
    hyperB_kernel<<<(NP + 127) / 128, 512>>>(W3, b3);
    hyper3_kernel<<<WIDTH, D_>>>();
    cnf_mma_kernel<<<GRID, 128>>>(z, out);
}